// round 14
// baseline (speedup 1.0000x reference)
#include <cuda_runtime.h>
#include <math.h>

typedef unsigned long long ull;

#define EMBD   300
#define UNITS  512
#define BATCH  64
#define TLEN   512
#define NC     3072   // 2 * 3 * UNITS

// scan decomposition: 128 blocks = 2 dir x 2 batch-halves x 32 unit-slabs
#define UPB    16     // units per block
#define BPG    32     // batches per group

// ---------------- scratch (device globals; no allocations allowed) ----------
__device__ float g_xw[(size_t)TLEN * NC * BATCH];          // [t][c][b]
// h stored DUPLICATED: each entry is pk2(h,h) — matvec consumes without MOVs
__device__ ull g_hd[2 * 2 * 2 * UNITS * BPG];              // [dir][bgrp][par][k][b32]

struct alignas(128) BarWord { unsigned int v; unsigned int pad[31]; };
__device__ BarWord g_cnt[4];
__device__ BarWord g_gen[4];

// ---------------- packed fp32x2 helpers -------------------------------------
__device__ __forceinline__ ull pk2(float lo, float hi) {
    ull r; asm("mov.b64 %0, {%1, %2};" : "=l"(r) : "f"(lo), "f"(hi)); return r;
}
__device__ __forceinline__ void fma2(ull& d, ull a, ull b) {
    asm("fma.rn.f32x2 %0, %1, %2, %0;" : "+l"(d) : "l"(a), "l"(b));
}
__device__ __forceinline__ float2 upk2(ull v) {
    float2 r; asm("mov.b64 {%0, %1}, %2;" : "=f"(r.x), "=f"(r.y) : "l"(v)); return r;
}

// ---------------- Kernel 1: embed gather + input GEMM (R11, unchanged) ------
#define EG_SMEM ((2*16*64 + 2*16*256) * 4)   // 40960 B
__global__ __launch_bounds__(256, 2) void embed_gemm(
    const int* __restrict__ tokens, const float* __restrict__ emb,
    const float* __restrict__ Wf, const float* __restrict__ Wb,
    const float* __restrict__ bf, const float* __restrict__ bb)
{
    extern __shared__ float dsm[];
    float* As = dsm;               // [buf][kk][64]
    float* Bs = As + 2 * 16 * 64;  // [buf][kk][256]

    const int t   = blockIdx.y;
    const int c0  = blockIdx.x * 256;
    const int tid = threadIdx.x;
    const int tx  = tid & 31;
    const int ty  = tid >> 5;

    const int arow = tid >> 2;
    const int akk  = (tid & 3) * 4;
    const int tok  = tokens[(size_t)arow * TLEN + t];
    const float* aptr = emb + (size_t)tok * EMBD;

    const int bkk = tid >> 4;
    const int bc0 = (tid & 15) * 16;
    const bool fwd = (c0 < 1536);
    const float* W   = fwd ? Wf : Wb;
    const int    wc0 = fwd ? c0 : (c0 - 1536);

    const int NT = (EMBD + 15) / 16;   // 19

    float ar_[4];
    float br_[16];

    {
        #pragma unroll
        for (int i = 0; i < 4; i++) {
            int k = akk + i;
            ar_[i] = (k < EMBD) ? __ldg(aptr + k) : 0.f;
        }
        const float* wp = W + (size_t)bkk * 1536 + wc0 + bc0;
        #pragma unroll
        for (int j = 0; j < 4; j++)
            *(float4*)(br_ + j * 4) = *(const float4*)(wp + j * 4);
        #pragma unroll
        for (int i = 0; i < 4; i++) As[(akk + i) * 64 + arow] = ar_[i];
        #pragma unroll
        for (int j = 0; j < 4; j++)
            *(float4*)&Bs[bkk * 256 + bc0 + j * 4] = *(float4*)(br_ + j * 4);
    }
    __syncthreads();

    ull acc[8][4];
    #pragma unroll
    for (int i = 0; i < 8; i++)
        #pragma unroll
        for (int j = 0; j < 4; j++) acc[i][j] = 0ull;

    for (int kt = 0; kt < NT; kt++) {
        const int cur = kt & 1;
        if (kt + 1 < NT) {
            const int k0 = (kt + 1) * 16;
            #pragma unroll
            for (int i = 0; i < 4; i++) {
                int k = k0 + akk + i;
                ar_[i] = (k < EMBD) ? __ldg(aptr + k) : 0.f;
            }
            int k = k0 + bkk;
            if (k < EMBD) {
                const float* wp = W + (size_t)k * 1536 + wc0 + bc0;
                #pragma unroll
                for (int j = 0; j < 4; j++)
                    *(float4*)(br_ + j * 4) = *(const float4*)(wp + j * 4);
            } else {
                #pragma unroll
                for (int j = 0; j < 4; j++)
                    *(float4*)(br_ + j * 4) = make_float4(0, 0, 0, 0);
            }
        }
        const float* Ab = As + cur * 1024;
        const float* Bb = Bs + cur * 4096;
        #pragma unroll
        for (int kk = 0; kk < 16; kk++) {
            const float4 a0 = *(const float4*)(Ab + kk * 64 + ty * 8);
            const float4 a1 = *(const float4*)(Ab + kk * 64 + ty * 8 + 4);
            const ulonglong2 b01 = *(const ulonglong2*)(Bb + kk * 256 + tx * 8);
            const ulonglong2 b23 = *(const ulonglong2*)(Bb + kk * 256 + tx * 8 + 4);
            const ull bp[4] = {b01.x, b01.y, b23.x, b23.y};
            const float av[8] = {a0.x, a0.y, a0.z, a0.w, a1.x, a1.y, a1.z, a1.w};
            #pragma unroll
            for (int i = 0; i < 8; i++) {
                const ull ad = pk2(av[i], av[i]);
                #pragma unroll
                for (int j = 0; j < 4; j++) fma2(acc[i][j], ad, bp[j]);
            }
        }
        if (kt + 1 < NT) {
            const int nxt = cur ^ 1;
            float* An = As + nxt * 1024;
            float* Bn = Bs + nxt * 4096;
            #pragma unroll
            for (int i = 0; i < 4; i++) An[(akk + i) * 64 + arow] = ar_[i];
            #pragma unroll
            for (int j = 0; j < 4; j++)
                *(float4*)&Bn[bkk * 256 + bc0 + j * 4] = *(float4*)(br_ + j * 4);
        }
        __syncthreads();
    }

    const float* bias = fwd ? bf : bb;
    #pragma unroll
    for (int j = 0; j < 4; j++) {
        const int ce = tx * 8 + j * 2;
        const float be = bias[wc0 + ce];
        const float bo = bias[wc0 + ce + 1];
        float ve[8], vo[8];
        #pragma unroll
        for (int i = 0; i < 8; i++) {
            const float2 v = upk2(acc[i][j]);
            ve[i] = v.x + be;
            vo[i] = v.y + bo;
        }
        float* de = g_xw + ((size_t)t * NC + c0 + ce) * BATCH + ty * 8;
        float* doo = de + BATCH;
        *(float4*)(de)      = make_float4(ve[0], ve[1], ve[2], ve[3]);
        *(float4*)(de + 4)  = make_float4(ve[4], ve[5], ve[6], ve[7]);
        *(float4*)(doo)     = make_float4(vo[0], vo[1], vo[2], vo[3]);
        *(float4*)(doo + 4) = make_float4(vo[4], vo[5], vo[6], vo[7]);
    }
}

// ---------------- split per-group barrier (32 blocks) ------------------------
__device__ __forceinline__ void bar_arrive(int gid, int nblk)
{
    __syncthreads();
    if (threadIdx.x == 0) {
        __threadfence();                  // release
        unsigned int my = atomicAdd(&g_cnt[gid].v, 1u);
        if (my == (unsigned)nblk - 1u) {
            *(volatile unsigned int*)&g_cnt[gid].v = 0u;
            __threadfence();
            atomicAdd(&g_gen[gid].v, 1u);
        }
    }
}
__device__ __forceinline__ void bar_wait(int gid, unsigned int gen0)
{
    if (threadIdx.x == 0) {
        while (*(volatile unsigned int*)&g_gen[gid].v == gen0) { }
        __threadfence();                  // acquire
    }
    __syncthreads();
}

// ---------------- Kernel 2: persistent bidirectional GRU scan ---------------
// 512 threads, 16 warps x 32 k each. Tile: 4u x 4b x 3 gates per thread.
// h pre-duplicated in g_hd (2x LDG.128 per k, zero packing MOVs).
// smem: Us[512][48] | part[16][3][32][18]
__global__ __launch_bounds__(512, 1) void gru_scan(
    const float* __restrict__ Uf, const float* __restrict__ Ub,
    const float* __restrict__ bf, const float* __restrict__ bb,
    float* __restrict__ out)
{
    extern __shared__ float sm[];
    float* Us   = sm;                    // 24576 floats (96KB)
    float* part = Us + 512 * 48;         // 16*3*576 = 27648 floats (108KB)
    __shared__ float brec[48];

    const int tid  = threadIdx.x;
    const int bid  = blockIdx.x;
    const int dir  = bid >> 6;
    const int bgrp = (bid >> 5) & 1;
    const int us   = bid & 31;
    const int gid  = dir * 2 + bgrp;
    const int u0   = us * UPB;
    const int B0   = bgrp * BPG;

    const float* U    = dir ? Ub : Uf;
    const float* brow = (dir ? bb : bf) + 1536;

    // U slab: Us[k][g*16+ui] = U[k][g*512 + u0 + ui]
    for (int l = tid; l < 512 * 48; l += 512) {
        int k = l / 48, j = l % 48;
        int g = j >> 4, ui = j & 15;
        Us[l] = U[(size_t)k * 1536 + g * 512 + u0 + ui];
    }
    if (tid < 48) brec[tid] = brow[(tid >> 4) * 512 + u0 + (tid & 15)];

    // zero duplicated h ping-pong: 131072 ull over 65536 threads -> 2 each
    {
        int l = (bid * 512 + tid) * 2;
        ulonglong2 z; z.x = 0ull; z.y = 0ull;
        *(ulonglong2*)(g_hd + l) = z;
    }
    unsigned int gen = *(volatile unsigned int*)&g_gen[gid].v;
    bar_arrive(gid, 32);
    bar_wait(gid, gen);
    gen++;

    // matvec tiling: warp = kh (16 warps x 32 k); lanes: uh(4) x bg(8)
    const int kh = tid >> 5;             // 0..15
    const int uh = tid & 3;              // units uh*4..uh*4+3
    const int bg = (tid >> 2) & 7;       // batches bg*4..bg*4+3

    // combine mapping: 1 output per thread
    const int cu = tid & 15;             // local unit
    const int cb = tid >> 4;             // batch 0..31

    // xw prefetch for step 0
    float xg[3];
    {
        const int t0 = dir ? (TLEN - 1) : 0;
        const float* xp = g_xw + ((size_t)t0 * NC + dir * 1536 + u0 + cu) * BATCH
                          + B0 + cb;
        #pragma unroll
        for (int g = 0; g < 3; g++)
            xg[g] = __ldg(xp + (size_t)g * 512 * BATCH);
    }

    for (int s = 0; s < TLEN; s++) {
        const int p = s & 1;
        const int t = dir ? (TLEN - 1 - s) : s;

        const ull* hbase = g_hd + (size_t)(gid * 2 + p) * UNITS * BPG;

        // prefetch h_old for combine (L2 latency hidden under matvec)
        const float hold = upk2(__ldg(hbase + (u0 + cu) * 32 + cb)).x;

        // matvec: 4 units x 4 batches x 3 gates over 32 k; dup-h from L2
        ull az[2][4], ar[2][4], ah[2][4];
        #pragma unroll
        for (int i = 0; i < 2; i++)
            #pragma unroll
            for (int j = 0; j < 4; j++) { az[i][j] = ar[i][j] = ah[i][j] = 0ull; }
        {
            const ull*   hp = hbase + (size_t)kh * 32 * 32 + bg * 4;
            const float* up = Us + (size_t)kh * 32 * 48 + uh * 4;
            #pragma unroll 1
            for (int kk = 0; kk < 32; kk += 4) {
                ulonglong2 h01[4], h23[4];
                #pragma unroll
                for (int j = 0; j < 4; j++) {
                    const ull* ha = hp + (size_t)(kk + j) * 32;
                    h01[j] = __ldg((const ulonglong2*)ha);
                    h23[j] = __ldg((const ulonglong2*)(ha + 2));
                }
                #pragma unroll
                for (int j = 0; j < 4; j++) {
                    const float* uk = up + (size_t)(kk + j) * 48;
                    const ulonglong2 z2 = *(const ulonglong2*)(uk);
                    const ulonglong2 r2 = *(const ulonglong2*)(uk + 16);
                    const ulonglong2 q2 = *(const ulonglong2*)(uk + 32);
                    const ull hd[4] = {h01[j].x, h01[j].y, h23[j].x, h23[j].y};
                    #pragma unroll
                    for (int b = 0; b < 4; b++) {
                        fma2(az[0][b], z2.x, hd[b]); fma2(az[1][b], z2.y, hd[b]);
                        fma2(ar[0][b], r2.x, hd[b]); fma2(ar[1][b], r2.y, hd[b]);
                        fma2(ah[0][b], q2.x, hd[b]); fma2(ah[1][b], q2.y, hd[b]);
                    }
                }
            }
        }
        // part[(kh*3+g)*576 + b*18 + u]
        {
            #pragma unroll
            for (int b = 0; b < 4; b++) {
                float* pb = part + kh * 3 * 576 + (bg * 4 + b) * 18 + uh * 4;
                *(ull*)(pb)            = az[0][b];
                *(ull*)(pb + 2)        = az[1][b];
                *(ull*)(pb + 576)      = ar[0][b];
                *(ull*)(pb + 576 + 2)  = ar[1][b];
                *(ull*)(pb + 1152)     = ah[0][b];
                *(ull*)(pb + 1152 + 2) = ah[1][b];
            }
        }
        __syncthreads();

        // combine: unit cu, batch cb — one h_new per thread
        float hn;
        {
            float rz = brec[cu], rr = brec[16 + cu], rh = brec[32 + cu];
            #pragma unroll
            for (int q = 0; q < 16; q++) {
                const float* pq = part + q * 3 * 576 + cb * 18 + cu;
                rz += pq[0];
                rr += pq[576];
                rh += pq[1152];
            }
            const float z  = 1.f / (1.f + expf(-(xg[0] + rz)));
            const float rg = 1.f / (1.f + expf(-(xg[1] + rr)));
            const float hh = tanhf(xg[2] + rg * rh);
            hn = z * hold + (1.f - z) * hh;

            ull* hw = g_hd + (size_t)(gid * 2 + (p ^ 1)) * UNITS * BPG;
            hw[(u0 + cu) * 32 + cb] = pk2(hn, hn);
        }
        bar_arrive(gid, 32);   // h published

        // ---- latency cover between arrive and wait ----
        out[((size_t)(B0 + cb) * TLEN + t) * 1024 + dir * 512 + u0 + cu] = hn;
        if (s == TLEN - 1)
            out[(size_t)BATCH * TLEN * 1024 + (size_t)(B0 + cb) * 1024
                + dir * 512 + u0 + cu] = hn;
        if (s + 1 < TLEN) {   // prefetch xw for next step
            const int tn = dir ? (TLEN - 2 - s) : (s + 1);
            const float* xp = g_xw + ((size_t)tn * NC + dir * 1536 + u0 + cu) * BATCH
                              + B0 + cb;
            #pragma unroll
            for (int g = 0; g < 3; g++)
                xg[g] = __ldg(xp + (size_t)g * 512 * BATCH);
        }
        bar_wait(gid, gen);
        gen++;
    }
}

// ---------------- launch ----------------------------------------------------
extern "C" void kernel_launch(void* const* d_in, const int* in_sizes, int n_in,
                              void* d_out, int out_size)
{
    const int*   tokens = (const int*)  d_in[0];
    const float* emb    = (const float*)d_in[1];
    const float* W_f    = (const float*)d_in[2];
    const float* U_f    = (const float*)d_in[3];
    const float* b_f    = (const float*)d_in[4];
    const float* W_b    = (const float*)d_in[5];
    const float* U_b    = (const float*)d_in[6];
    const float* b_b    = (const float*)d_in[7];
    float* out = (float*)d_out;

    (void)in_sizes; (void)n_in; (void)out_size;

    cudaFuncSetAttribute(embed_gemm, cudaFuncAttributeMaxDynamicSharedMemorySize,
                         EG_SMEM);
    dim3 g1(NC / 256, TLEN);
    embed_gemm<<<g1, 256, EG_SMEM>>>(tokens, emb, W_f, W_b, b_f, b_b);

    const size_t smem = (512 * 48 + 16 * 3 * 576) * sizeof(float); // 208896
    cudaFuncSetAttribute(gru_scan, cudaFuncAttributeMaxDynamicSharedMemorySize,
                         (int)smem);
    gru_scan<<<128, 512, smem>>>(U_f, U_b, b_f, b_b, out);
}

// round 15
// speedup vs baseline: 1.0380x; 1.0380x over previous
#include <cuda_runtime.h>
#include <math.h>

typedef unsigned long long ull;

#define EMBD   300
#define UNITS  512
#define BATCH  64
#define TLEN   512
#define NC     3072   // 2 * 3 * UNITS

// scan decomposition: 128 blocks = 2 dir x 2 batch-halves x 32 unit-slabs
#define UPB    16     // units per block
#define BPG    32     // batches per group

// ---------------- scratch (device globals; no allocations allowed) ----------
__device__ float g_xw[(size_t)TLEN * NC * BATCH];          // [t][c][b]
__device__ float g_h[2 * 2 * 2 * UNITS * BPG];             // [dir][bgrp][par][k][b32]

struct alignas(128) BarWord { unsigned int v; unsigned int pad[31]; };
__device__ BarWord g_cnt[4];
__device__ BarWord g_gen[4];

// ---------------- packed fp32x2 helpers -------------------------------------
__device__ __forceinline__ ull pk2(float lo, float hi) {
    ull r; asm("mov.b64 %0, {%1, %2};" : "=l"(r) : "f"(lo), "f"(hi)); return r;
}
__device__ __forceinline__ void fma2(ull& d, ull a, ull b) {
    asm("fma.rn.f32x2 %0, %1, %2, %0;" : "+l"(d) : "l"(a), "l"(b));
}
__device__ __forceinline__ float2 upk2(ull v) {
    float2 r; asm("mov.b64 {%0, %1}, %2;" : "=f"(r.x), "=f"(r.y) : "l"(v)); return r;
}

// ---------------- Kernel 1: embed gather + input GEMM (R11, unchanged) ------
#define EG_SMEM ((2*16*64 + 2*16*256) * 4)   // 40960 B
__global__ __launch_bounds__(256, 2) void embed_gemm(
    const int* __restrict__ tokens, const float* __restrict__ emb,
    const float* __restrict__ Wf, const float* __restrict__ Wb,
    const float* __restrict__ bf, const float* __restrict__ bb)
{
    extern __shared__ float dsm[];
    float* As = dsm;               // [buf][kk][64]
    float* Bs = As + 2 * 16 * 64;  // [buf][kk][256]

    const int t   = blockIdx.y;
    const int c0  = blockIdx.x * 256;
    const int tid = threadIdx.x;
    const int tx  = tid & 31;
    const int ty  = tid >> 5;

    const int arow = tid >> 2;
    const int akk  = (tid & 3) * 4;
    const int tok  = tokens[(size_t)arow * TLEN + t];
    const float* aptr = emb + (size_t)tok * EMBD;

    const int bkk = tid >> 4;
    const int bc0 = (tid & 15) * 16;
    const bool fwd = (c0 < 1536);
    const float* W   = fwd ? Wf : Wb;
    const int    wc0 = fwd ? c0 : (c0 - 1536);

    const int NT = (EMBD + 15) / 16;   // 19

    float ar_[4];
    float br_[16];

    {
        #pragma unroll
        for (int i = 0; i < 4; i++) {
            int k = akk + i;
            ar_[i] = (k < EMBD) ? __ldg(aptr + k) : 0.f;
        }
        const float* wp = W + (size_t)bkk * 1536 + wc0 + bc0;
        #pragma unroll
        for (int j = 0; j < 4; j++)
            *(float4*)(br_ + j * 4) = *(const float4*)(wp + j * 4);
        #pragma unroll
        for (int i = 0; i < 4; i++) As[(akk + i) * 64 + arow] = ar_[i];
        #pragma unroll
        for (int j = 0; j < 4; j++)
            *(float4*)&Bs[bkk * 256 + bc0 + j * 4] = *(float4*)(br_ + j * 4);
    }
    __syncthreads();

    ull acc[8][4];
    #pragma unroll
    for (int i = 0; i < 8; i++)
        #pragma unroll
        for (int j = 0; j < 4; j++) acc[i][j] = 0ull;

    for (int kt = 0; kt < NT; kt++) {
        const int cur = kt & 1;
        if (kt + 1 < NT) {
            const int k0 = (kt + 1) * 16;
            #pragma unroll
            for (int i = 0; i < 4; i++) {
                int k = k0 + akk + i;
                ar_[i] = (k < EMBD) ? __ldg(aptr + k) : 0.f;
            }
            int k = k0 + bkk;
            if (k < EMBD) {
                const float* wp = W + (size_t)k * 1536 + wc0 + bc0;
                #pragma unroll
                for (int j = 0; j < 4; j++)
                    *(float4*)(br_ + j * 4) = *(const float4*)(wp + j * 4);
            } else {
                #pragma unroll
                for (int j = 0; j < 4; j++)
                    *(float4*)(br_ + j * 4) = make_float4(0, 0, 0, 0);
            }
        }
        const float* Ab = As + cur * 1024;
        const float* Bb = Bs + cur * 4096;
        #pragma unroll
        for (int kk = 0; kk < 16; kk++) {
            const float4 a0 = *(const float4*)(Ab + kk * 64 + ty * 8);
            const float4 a1 = *(const float4*)(Ab + kk * 64 + ty * 8 + 4);
            const ulonglong2 b01 = *(const ulonglong2*)(Bb + kk * 256 + tx * 8);
            const ulonglong2 b23 = *(const ulonglong2*)(Bb + kk * 256 + tx * 8 + 4);
            const ull bp[4] = {b01.x, b01.y, b23.x, b23.y};
            const float av[8] = {a0.x, a0.y, a0.z, a0.w, a1.x, a1.y, a1.z, a1.w};
            #pragma unroll
            for (int i = 0; i < 8; i++) {
                const ull ad = pk2(av[i], av[i]);
                #pragma unroll
                for (int j = 0; j < 4; j++) fma2(acc[i][j], ad, bp[j]);
            }
        }
        if (kt + 1 < NT) {
            const int nxt = cur ^ 1;
            float* An = As + nxt * 1024;
            float* Bn = Bs + nxt * 4096;
            #pragma unroll
            for (int i = 0; i < 4; i++) An[(akk + i) * 64 + arow] = ar_[i];
            #pragma unroll
            for (int j = 0; j < 4; j++)
                *(float4*)&Bn[bkk * 256 + bc0 + j * 4] = *(float4*)(br_ + j * 4);
        }
        __syncthreads();
    }

    const float* bias = fwd ? bf : bb;
    #pragma unroll
    for (int j = 0; j < 4; j++) {
        const int ce = tx * 8 + j * 2;
        const float be = bias[wc0 + ce];
        const float bo = bias[wc0 + ce + 1];
        float ve[8], vo[8];
        #pragma unroll
        for (int i = 0; i < 8; i++) {
            const float2 v = upk2(acc[i][j]);
            ve[i] = v.x + be;
            vo[i] = v.y + bo;
        }
        float* de = g_xw + ((size_t)t * NC + c0 + ce) * BATCH + ty * 8;
        float* doo = de + BATCH;
        *(float4*)(de)      = make_float4(ve[0], ve[1], ve[2], ve[3]);
        *(float4*)(de + 4)  = make_float4(ve[4], ve[5], ve[6], ve[7]);
        *(float4*)(doo)     = make_float4(vo[0], vo[1], vo[2], vo[3]);
        *(float4*)(doo + 4) = make_float4(vo[4], vo[5], vo[6], vo[7]);
    }
}

// ---------------- split per-group barrier (32 blocks) ------------------------
__device__ __forceinline__ void bar_arrive(int gid, int nblk)
{
    __syncthreads();
    if (threadIdx.x == 0) {
        __threadfence();                  // release
        unsigned int my = atomicAdd(&g_cnt[gid].v, 1u);
        if (my == (unsigned)nblk - 1u) {
            *(volatile unsigned int*)&g_cnt[gid].v = 0u;
            __threadfence();
            atomicAdd(&g_gen[gid].v, 1u);
        }
    }
}
__device__ __forceinline__ void bar_wait(int gid, unsigned int gen0)
{
    if (threadIdx.x == 0) {
        while (*(volatile unsigned int*)&g_gen[gid].v == gen0) { }
        __threadfence();                  // acquire
    }
    __syncthreads();
}

// ---------------- Kernel 2: persistent bidirectional GRU scan ---------------
// 256 threads (R12 config). Matvec restructured: per 4-k batch, ALL 16 loads
// (4 LDG.128 h + 12 LDS.128 U) issue before the 96 FMA2s — load latency is
// covered by the load batch itself (MLP 16), not by extra warps.
// smem: Us[512][48] | part[8][3][32][18]
__global__ __launch_bounds__(256, 1) void gru_scan(
    const float* __restrict__ Uf, const float* __restrict__ Ub,
    const float* __restrict__ bf, const float* __restrict__ bb,
    float* __restrict__ out)
{
    extern __shared__ float sm[];
    float* Us   = sm;                    // 24576 floats (96KB)
    float* part = Us + 512 * 48;         // 8*3*576 = 13824 floats (54KB)
    __shared__ float brec[48];

    const int tid  = threadIdx.x;
    const int bid  = blockIdx.x;
    const int dir  = bid >> 6;
    const int bgrp = (bid >> 5) & 1;
    const int us   = bid & 31;
    const int gid  = dir * 2 + bgrp;
    const int u0   = us * UPB;
    const int B0   = bgrp * BPG;

    const float* U    = dir ? Ub : Uf;
    const float* brow = (dir ? bb : bf) + 1536;

    // U slab: Us[k][g*16+ui] = U[k][g*512 + u0 + ui]
    for (int l = tid; l < 512 * 48; l += 256) {
        int k = l / 48, j = l % 48;
        int g = j >> 4, ui = j & 15;
        Us[l] = U[(size_t)k * 1536 + g * 512 + u0 + ui];
    }
    if (tid < 48) brec[tid] = brow[(tid >> 4) * 512 + u0 + (tid & 15)];

    // zero h ping-pong
    {
        int l = (bid * 256 + tid) * 4;
        *(float4*)(g_h + l) = make_float4(0.f, 0.f, 0.f, 0.f);
    }
    unsigned int gen = *(volatile unsigned int*)&g_gen[gid].v;
    bar_arrive(gid, 32);
    bar_wait(gid, gen);
    gen++;

    // matvec tiling: warp = kh (8 warps x 64 k); lanes: uh(4) x bg(8)
    const int kh = tid >> 5;
    const int uh = tid & 3;              // units uh*4..uh*4+3
    const int bg = (tid >> 2) & 7;       // batches bg*4..bg*4+3

    // combine mapping: 2 outputs per thread
    const int cu2 = tid & 7;             // unit pair cu2*2, cu2*2+1
    const int cb  = tid >> 3;            // batch 0..31

    // xw prefetch for step 0
    float xg[6];
    {
        const int t0 = dir ? (TLEN - 1) : 0;
        const float* xp = g_xw + ((size_t)t0 * NC + dir * 1536 + u0 + cu2 * 2) * BATCH
                          + B0 + cb;
        #pragma unroll
        for (int g = 0; g < 3; g++) {
            xg[g * 2]     = __ldg(xp + (size_t)g * 512 * BATCH);
            xg[g * 2 + 1] = __ldg(xp + ((size_t)g * 512 + 1) * BATCH);
        }
    }

    for (int s = 0; s < TLEN; s++) {
        const int p = s & 1;
        const int t = dir ? (TLEN - 1 - s) : s;

        const float* hbase = g_h + (size_t)(gid * 2 + p) * UNITS * BPG;

        // prefetch h_old for combine (L2 latency hidden under matvec)
        const float hold0 = __ldg(hbase + (u0 + cu2 * 2) * 32 + cb);
        const float hold1 = __ldg(hbase + (u0 + cu2 * 2 + 1) * 32 + cb);

        // matvec: 4u x 4b x 3 gates over 64 k, 4-k load-batched
        ull az[2][4], ar[2][4], ah[2][4];
        #pragma unroll
        for (int i = 0; i < 2; i++)
            #pragma unroll
            for (int j = 0; j < 4; j++) { az[i][j] = ar[i][j] = ah[i][j] = 0ull; }
        {
            const float4* hp = (const float4*)(hbase + (size_t)kh * 64 * 32 + bg * 4);
            const float*  up = Us + (size_t)kh * 64 * 48 + uh * 4;
            #pragma unroll 1
            for (int kk = 0; kk < 64; kk += 4) {
                // ---- load phase: 4 LDG.128 + 12 LDS.128, no consumers ----
                float4 hb[4];
                ulonglong2 zb[4], rb[4], qb[4];
                #pragma unroll
                for (int j = 0; j < 4; j++)
                    hb[j] = __ldg(hp + (size_t)(kk + j) * 8);
                #pragma unroll
                for (int j = 0; j < 4; j++) {
                    const float* uk = up + (size_t)(kk + j) * 48;
                    zb[j] = *(const ulonglong2*)(uk);
                    rb[j] = *(const ulonglong2*)(uk + 16);
                    qb[j] = *(const ulonglong2*)(uk + 32);
                }
                // ---- compute phase: 96 FMA2 ----
                #pragma unroll
                for (int j = 0; j < 4; j++) {
                    const ull hd[4] = {pk2(hb[j].x, hb[j].x), pk2(hb[j].y, hb[j].y),
                                       pk2(hb[j].z, hb[j].z), pk2(hb[j].w, hb[j].w)};
                    #pragma unroll
                    for (int b = 0; b < 4; b++) {
                        fma2(az[0][b], zb[j].x, hd[b]); fma2(az[1][b], zb[j].y, hd[b]);
                        fma2(ar[0][b], rb[j].x, hd[b]); fma2(ar[1][b], rb[j].y, hd[b]);
                        fma2(ah[0][b], qb[j].x, hd[b]); fma2(ah[1][b], qb[j].y, hd[b]);
                    }
                }
            }
        }
        // part[(kh*3+g)*576 + b*18 + u]
        {
            #pragma unroll
            for (int b = 0; b < 4; b++) {
                float* pb = part + kh * 3 * 576 + (bg * 4 + b) * 18 + uh * 4;
                *(ull*)(pb)            = az[0][b];
                *(ull*)(pb + 2)        = az[1][b];
                *(ull*)(pb + 576)      = ar[0][b];
                *(ull*)(pb + 576 + 2)  = ar[1][b];
                *(ull*)(pb + 1152)     = ah[0][b];
                *(ull*)(pb + 1152 + 2) = ah[1][b];
            }
        }
        __syncthreads();

        // combine: units cu2*2, cu2*2+1; batch cb
        float hn0, hn1;
        {
            float rz0 = brec[cu2 * 2],      rz1 = brec[cu2 * 2 + 1];
            float rr0 = brec[16 + cu2 * 2], rr1 = brec[16 + cu2 * 2 + 1];
            float rh0 = brec[32 + cu2 * 2], rh1 = brec[32 + cu2 * 2 + 1];
            #pragma unroll
            for (int q = 0; q < 8; q++) {
                const float* pq = part + q * 3 * 576 + cb * 18 + cu2 * 2;
                float2 v;
                v = upk2(*(const ull*)(pq));        rz0 += v.x; rz1 += v.y;
                v = upk2(*(const ull*)(pq + 576));  rr0 += v.x; rr1 += v.y;
                v = upk2(*(const ull*)(pq + 1152)); rh0 += v.x; rh1 += v.y;
            }
            const float z0 = 1.f / (1.f + expf(-(xg[0] + rz0)));
            const float z1 = 1.f / (1.f + expf(-(xg[1] + rz1)));
            const float r0 = 1.f / (1.f + expf(-(xg[2] + rr0)));
            const float r1 = 1.f / (1.f + expf(-(xg[3] + rr1)));
            const float c0 = tanhf(xg[4] + r0 * rh0);
            const float c1 = tanhf(xg[5] + r1 * rh1);
            hn0 = z0 * hold0 + (1.f - z0) * c0;
            hn1 = z1 * hold1 + (1.f - z1) * c1;

            float* hw = g_h + (size_t)(gid * 2 + (p ^ 1)) * UNITS * BPG;
            hw[(u0 + cu2 * 2) * 32 + cb]     = hn0;
            hw[(u0 + cu2 * 2 + 1) * 32 + cb] = hn1;
        }
        bar_arrive(gid, 32);   // h published

        // ---- latency cover between arrive and wait ----
        {
            float2 o2 = make_float2(hn0, hn1);
            *(float2*)(out + ((size_t)(B0 + cb) * TLEN + t) * 1024
                           + dir * 512 + u0 + cu2 * 2) = o2;
            if (s == TLEN - 1)
                *(float2*)(out + (size_t)BATCH * TLEN * 1024
                               + (size_t)(B0 + cb) * 1024
                               + dir * 512 + u0 + cu2 * 2) = o2;
        }
        if (s + 1 < TLEN) {   // prefetch xw for next step
            const int tn = dir ? (TLEN - 2 - s) : (s + 1);
            const float* xp = g_xw + ((size_t)tn * NC + dir * 1536 + u0 + cu2 * 2) * BATCH
                              + B0 + cb;
            #pragma unroll
            for (int g = 0; g < 3; g++) {
                xg[g * 2]     = __ldg(xp + (size_t)g * 512 * BATCH);
                xg[g * 2 + 1] = __ldg(xp + ((size_t)g * 512 + 1) * BATCH);
            }
        }
        bar_wait(gid, gen);
        gen++;
    }
}

// ---------------- launch ----------------------------------------------------
extern "C" void kernel_launch(void* const* d_in, const int* in_sizes, int n_in,
                              void* d_out, int out_size)
{
    const int*   tokens = (const int*)  d_in[0];
    const float* emb    = (const float*)d_in[1];
    const float* W_f    = (const float*)d_in[2];
    const float* U_f    = (const float*)d_in[3];
    const float* b_f    = (const float*)d_in[4];
    const float* W_b    = (const float*)d_in[5];
    const float* U_b    = (const float*)d_in[6];
    const float* b_b    = (const float*)d_in[7];
    float* out = (float*)d_out;

    (void)in_sizes; (void)n_in; (void)out_size;

    cudaFuncSetAttribute(embed_gemm, cudaFuncAttributeMaxDynamicSharedMemorySize,
                         EG_SMEM);
    dim3 g1(NC / 256, TLEN);
    embed_gemm<<<g1, 256, EG_SMEM>>>(tokens, emb, W_f, W_b, b_f, b_b);

    const size_t smem = (512 * 48 + 24 * 576) * sizeof(float); // 153600
    cudaFuncSetAttribute(gru_scan, cudaFuncAttributeMaxDynamicSharedMemorySize,
                         (int)smem);
    gru_scan<<<128, 256, smem>>>(U_f, U_b, b_f, b_b, out);
}

// round 16
// speedup vs baseline: 1.1364x; 1.0949x over previous
#include <cuda_runtime.h>
#include <math.h>

typedef unsigned long long ull;

#define EMBD   300
#define UNITS  512
#define BATCH  64
#define TLEN   512
#define NC     3072   // 2 * 3 * UNITS
#define TILES_PER_T 12   // NC / 256 embed blocks per timestep

// scan decomposition: 128 blocks = 2 dir x 2 batch-halves x 32 unit-slabs
#define UPB    16     // units per block
#define BPG    32     // batches per group

// ---------------- scratch (device globals; no allocations allowed) ----------
__device__ float g_xw[(size_t)TLEN * NC * BATCH];          // [t][c][b]
__device__ float g_h[2 * 2 * 2 * UNITS * BPG];             // [dir][bgrp][par][k][b32]
__device__ unsigned int g_done[TLEN];                      // embed->scan ready flags

struct alignas(128) BarWord { unsigned int v; unsigned int pad[31]; };
__device__ BarWord g_cnt[5];   // 4 scan groups + 1 full-grid (reset) barrier
__device__ BarWord g_gen[5];

// ---------------- packed fp32x2 helpers -------------------------------------
__device__ __forceinline__ ull pk2(float lo, float hi) {
    ull r; asm("mov.b64 %0, {%1, %2};" : "=l"(r) : "f"(lo), "f"(hi)); return r;
}
__device__ __forceinline__ void fma2(ull& d, ull a, ull b) {
    asm("fma.rn.f32x2 %0, %1, %2, %0;" : "+l"(d) : "l"(a), "l"(b));
}
__device__ __forceinline__ float2 upk2(ull v) {
    float2 r; asm("mov.b64 {%0, %1}, %2;" : "=f"(r.x), "=f"(r.y) : "l"(v)); return r;
}

// ---------------- Kernel 1: embed gather + input GEMM (R11 core) ------------
// grid (12, 512); t interleaved 0,511,1,510,... so both scan fronts are fed.
// After stores: fenced flag increment on g_done[t].
#define EG_SMEM ((2*16*64 + 2*16*256) * 4)   // 40960 B
__global__ __launch_bounds__(256, 2) void embed_gemm(
    const int* __restrict__ tokens, const float* __restrict__ emb,
    const float* __restrict__ Wf, const float* __restrict__ Wb,
    const float* __restrict__ bf, const float* __restrict__ bb)
{
    extern __shared__ float dsm[];
    float* As = dsm;               // [buf][kk][64]
    float* Bs = As + 2 * 16 * 64;  // [buf][kk][256]

    const int by  = blockIdx.y;
    const int t   = (by & 1) ? (TLEN - 1 - (by >> 1)) : (by >> 1);
    const int c0  = blockIdx.x * 256;
    const int tid = threadIdx.x;
    const int tx  = tid & 31;
    const int ty  = tid >> 5;

    const int arow = tid >> 2;
    const int akk  = (tid & 3) * 4;
    const int tok  = tokens[(size_t)arow * TLEN + t];
    const float* aptr = emb + (size_t)tok * EMBD;

    const int bkk = tid >> 4;
    const int bc0 = (tid & 15) * 16;
    const bool fwd = (c0 < 1536);
    const float* W   = fwd ? Wf : Wb;
    const int    wc0 = fwd ? c0 : (c0 - 1536);

    const int NT = (EMBD + 15) / 16;   // 19

    float ar_[4];
    float br_[16];

    {
        #pragma unroll
        for (int i = 0; i < 4; i++) {
            int k = akk + i;
            ar_[i] = (k < EMBD) ? __ldg(aptr + k) : 0.f;
        }
        const float* wp = W + (size_t)bkk * 1536 + wc0 + bc0;
        #pragma unroll
        for (int j = 0; j < 4; j++)
            *(float4*)(br_ + j * 4) = *(const float4*)(wp + j * 4);
        #pragma unroll
        for (int i = 0; i < 4; i++) As[(akk + i) * 64 + arow] = ar_[i];
        #pragma unroll
        for (int j = 0; j < 4; j++)
            *(float4*)&Bs[bkk * 256 + bc0 + j * 4] = *(float4*)(br_ + j * 4);
    }
    __syncthreads();

    ull acc[8][4];
    #pragma unroll
    for (int i = 0; i < 8; i++)
        #pragma unroll
        for (int j = 0; j < 4; j++) acc[i][j] = 0ull;

    for (int kt = 0; kt < NT; kt++) {
        const int cur = kt & 1;
        if (kt + 1 < NT) {
            const int k0 = (kt + 1) * 16;
            #pragma unroll
            for (int i = 0; i < 4; i++) {
                int k = k0 + akk + i;
                ar_[i] = (k < EMBD) ? __ldg(aptr + k) : 0.f;
            }
            int k = k0 + bkk;
            if (k < EMBD) {
                const float* wp = W + (size_t)k * 1536 + wc0 + bc0;
                #pragma unroll
                for (int j = 0; j < 4; j++)
                    *(float4*)(br_ + j * 4) = *(const float4*)(wp + j * 4);
            } else {
                #pragma unroll
                for (int j = 0; j < 4; j++)
                    *(float4*)(br_ + j * 4) = make_float4(0, 0, 0, 0);
            }
        }
        const float* Ab = As + cur * 1024;
        const float* Bb = Bs + cur * 4096;
        #pragma unroll
        for (int kk = 0; kk < 16; kk++) {
            const float4 a0 = *(const float4*)(Ab + kk * 64 + ty * 8);
            const float4 a1 = *(const float4*)(Ab + kk * 64 + ty * 8 + 4);
            const ulonglong2 b01 = *(const ulonglong2*)(Bb + kk * 256 + tx * 8);
            const ulonglong2 b23 = *(const ulonglong2*)(Bb + kk * 256 + tx * 8 + 4);
            const ull bp[4] = {b01.x, b01.y, b23.x, b23.y};
            const float av[8] = {a0.x, a0.y, a0.z, a0.w, a1.x, a1.y, a1.z, a1.w};
            #pragma unroll
            for (int i = 0; i < 8; i++) {
                const ull ad = pk2(av[i], av[i]);
                #pragma unroll
                for (int j = 0; j < 4; j++) fma2(acc[i][j], ad, bp[j]);
            }
        }
        if (kt + 1 < NT) {
            const int nxt = cur ^ 1;
            float* An = As + nxt * 1024;
            float* Bn = Bs + nxt * 4096;
            #pragma unroll
            for (int i = 0; i < 4; i++) An[(akk + i) * 64 + arow] = ar_[i];
            #pragma unroll
            for (int j = 0; j < 4; j++)
                *(float4*)&Bn[bkk * 256 + bc0 + j * 4] = *(float4*)(br_ + j * 4);
        }
        __syncthreads();
    }

    const float* bias = fwd ? bf : bb;
    #pragma unroll
    for (int j = 0; j < 4; j++) {
        const int ce = tx * 8 + j * 2;
        const float be = bias[wc0 + ce];
        const float bo = bias[wc0 + ce + 1];
        float ve[8], vo[8];
        #pragma unroll
        for (int i = 0; i < 8; i++) {
            const float2 v = upk2(acc[i][j]);
            ve[i] = v.x + be;
            vo[i] = v.y + bo;
        }
        float* de = g_xw + ((size_t)t * NC + c0 + ce) * BATCH + ty * 8;
        float* doo = de + BATCH;
        *(float4*)(de)      = make_float4(ve[0], ve[1], ve[2], ve[3]);
        *(float4*)(de + 4)  = make_float4(ve[4], ve[5], ve[6], ve[7]);
        *(float4*)(doo)     = make_float4(vo[0], vo[1], vo[2], vo[3]);
        *(float4*)(doo + 4) = make_float4(vo[4], vo[5], vo[6], vo[7]);
    }

    // publish: this tile of xw[t] is ready
    __threadfence();
    __syncthreads();
    if (tid == 0) atomicAdd(&g_done[t], 1u);
}

// ---------------- split per-group barrier ------------------------------------
__device__ __forceinline__ void bar_arrive(int gid, int nblk)
{
    __syncthreads();
    if (threadIdx.x == 0) {
        __threadfence();                  // release
        unsigned int my = atomicAdd(&g_cnt[gid].v, 1u);
        if (my == (unsigned)nblk - 1u) {
            *(volatile unsigned int*)&g_cnt[gid].v = 0u;
            __threadfence();
            atomicAdd(&g_gen[gid].v, 1u);
        }
    }
}
__device__ __forceinline__ void bar_wait(int gid, unsigned int gen0)
{
    if (threadIdx.x == 0) {
        while (*(volatile unsigned int*)&g_gen[gid].v == gen0) { }
        __threadfence();                  // acquire
    }
    __syncthreads();
}

// ---------------- Kernel 2: persistent bidirectional GRU scan (R12 body) ----
// Runs CONCURRENTLY with embed_gemm; waits on g_done[t] before consuming xw[t].
// smem: Us[512][48] | part[8][3][32][18]
__global__ __launch_bounds__(256, 1) void gru_scan(
    const float* __restrict__ Uf, const float* __restrict__ Ub,
    const float* __restrict__ bf, const float* __restrict__ bb,
    float* __restrict__ out)
{
    extern __shared__ float sm[];
    float* Us   = sm;                    // 24576 floats (96KB)
    float* part = Us + 512 * 48;         // 8*3*576 = 13824 floats (54KB)
    __shared__ float brec[48];

    const int tid  = threadIdx.x;
    const int bid  = blockIdx.x;
    const int dir  = bid >> 6;
    const int bgrp = (bid >> 5) & 1;
    const int us   = bid & 31;
    const int gid  = dir * 2 + bgrp;
    const int u0   = us * UPB;
    const int B0   = bgrp * BPG;

    const float* U    = dir ? Ub : Uf;
    const float* brow = (dir ? bb : bf) + 1536;

    // U slab: Us[k][g*16+ui] = U[k][g*512 + u0 + ui]
    for (int l = tid; l < 512 * 48; l += 256) {
        int k = l / 48, j = l % 48;
        int g = j >> 4, ui = j & 15;
        Us[l] = U[(size_t)k * 1536 + g * 512 + u0 + ui];
    }
    if (tid < 48) brec[tid] = brow[(tid >> 4) * 512 + u0 + (tid & 15)];

    // zero h ping-pong
    {
        int l = (bid * 256 + tid) * 4;
        *(float4*)(g_h + l) = make_float4(0.f, 0.f, 0.f, 0.f);
    }
    unsigned int gen = *(volatile unsigned int*)&g_gen[gid].v;
    bar_arrive(gid, 32);
    bar_wait(gid, gen);
    gen++;

    // matvec tiling: warp = kh (8 warps x 64 k); lanes: uh(4) x bg(8)
    const int kh = tid >> 5;
    const int uh = tid & 3;              // units uh*4..uh*4+3
    const int bg = (tid >> 2) & 7;       // batches bg*4..bg*4+3

    // combine mapping: 2 outputs per thread
    const int cu2 = tid & 7;             // unit pair cu2*2, cu2*2+1
    const int cb  = tid >> 3;            // batch 0..31

    // xw prefetch for step 0 (wait for producer first)
    float xg[6];
    {
        const int t0 = dir ? (TLEN - 1) : 0;
        while (*(volatile unsigned int*)&g_done[t0] < (unsigned)TILES_PER_T) { }
        const float* xp = g_xw + ((size_t)t0 * NC + dir * 1536 + u0 + cu2 * 2) * BATCH
                          + B0 + cb;
        #pragma unroll
        for (int g = 0; g < 3; g++) {
            xg[g * 2]     = __ldg(xp + (size_t)g * 512 * BATCH);
            xg[g * 2 + 1] = __ldg(xp + ((size_t)g * 512 + 1) * BATCH);
        }
    }

    for (int s = 0; s < TLEN; s++) {
        const int p = s & 1;
        const int t = dir ? (TLEN - 1 - s) : s;

        const float* hbase = g_h + (size_t)(gid * 2 + p) * UNITS * BPG;

        // prefetch h_old for combine (L2 latency hidden under matvec)
        const float hold0 = __ldg(hbase + (u0 + cu2 * 2) * 32 + cb);
        const float hold1 = __ldg(hbase + (u0 + cu2 * 2 + 1) * 32 + cb);

        // matvec: 4 units x 4 batches x 3 gates over 64 k; h from L2, 8-deep
        ull az[2][4], ar[2][4], ah[2][4];
        #pragma unroll
        for (int i = 0; i < 2; i++)
            #pragma unroll
            for (int j = 0; j < 4; j++) { az[i][j] = ar[i][j] = ah[i][j] = 0ull; }
        {
            const float4* hp = (const float4*)(hbase + (size_t)kh * 64 * 32 + bg * 4);
            const float*  up = Us + (size_t)kh * 64 * 48 + uh * 4;
            #pragma unroll 1
            for (int kk = 0; kk < 64; kk += 8) {
                float4 hbuf[8];
                #pragma unroll
                for (int j = 0; j < 8; j++)
                    hbuf[j] = __ldg(hp + (size_t)(kk + j) * 8);
                #pragma unroll
                for (int j = 0; j < 8; j++) {
                    const float* uk = up + (size_t)(kk + j) * 48;
                    const ulonglong2 z2 = *(const ulonglong2*)(uk);
                    const ulonglong2 r2 = *(const ulonglong2*)(uk + 16);
                    const ulonglong2 q2 = *(const ulonglong2*)(uk + 32);
                    const ull hd[4] = {pk2(hbuf[j].x, hbuf[j].x),
                                       pk2(hbuf[j].y, hbuf[j].y),
                                       pk2(hbuf[j].z, hbuf[j].z),
                                       pk2(hbuf[j].w, hbuf[j].w)};
                    #pragma unroll
                    for (int b = 0; b < 4; b++) {
                        fma2(az[0][b], z2.x, hd[b]); fma2(az[1][b], z2.y, hd[b]);
                        fma2(ar[0][b], r2.x, hd[b]); fma2(ar[1][b], r2.y, hd[b]);
                        fma2(ah[0][b], q2.x, hd[b]); fma2(ah[1][b], q2.y, hd[b]);
                    }
                }
            }
        }
        // part[(kh*3+g)*576 + b*18 + u]
        {
            #pragma unroll
            for (int b = 0; b < 4; b++) {
                float* pb = part + kh * 3 * 576 + (bg * 4 + b) * 18 + uh * 4;
                *(ull*)(pb)            = az[0][b];
                *(ull*)(pb + 2)        = az[1][b];
                *(ull*)(pb + 576)      = ar[0][b];
                *(ull*)(pb + 576 + 2)  = ar[1][b];
                *(ull*)(pb + 1152)     = ah[0][b];
                *(ull*)(pb + 1152 + 2) = ah[1][b];
            }
        }
        __syncthreads();

        // combine: units cu2*2, cu2*2+1; batch cb
        float hn0, hn1;
        {
            float rz0 = brec[cu2 * 2],      rz1 = brec[cu2 * 2 + 1];
            float rr0 = brec[16 + cu2 * 2], rr1 = brec[16 + cu2 * 2 + 1];
            float rh0 = brec[32 + cu2 * 2], rh1 = brec[32 + cu2 * 2 + 1];
            #pragma unroll
            for (int q = 0; q < 8; q++) {
                const float* pq = part + q * 3 * 576 + cb * 18 + cu2 * 2;
                float2 v;
                v = upk2(*(const ull*)(pq));        rz0 += v.x; rz1 += v.y;
                v = upk2(*(const ull*)(pq + 576));  rr0 += v.x; rr1 += v.y;
                v = upk2(*(const ull*)(pq + 1152)); rh0 += v.x; rh1 += v.y;
            }
            const float z0 = 1.f / (1.f + expf(-(xg[0] + rz0)));
            const float z1 = 1.f / (1.f + expf(-(xg[1] + rz1)));
            const float r0 = 1.f / (1.f + expf(-(xg[2] + rr0)));
            const float r1 = 1.f / (1.f + expf(-(xg[3] + rr1)));
            const float c0 = tanhf(xg[4] + r0 * rh0);
            const float c1 = tanhf(xg[5] + r1 * rh1);
            hn0 = z0 * hold0 + (1.f - z0) * c0;
            hn1 = z1 * hold1 + (1.f - z1) * c1;

            float* hw = g_h + (size_t)(gid * 2 + (p ^ 1)) * UNITS * BPG;
            hw[(u0 + cu2 * 2) * 32 + cb]     = hn0;
            hw[(u0 + cu2 * 2 + 1) * 32 + cb] = hn1;
        }
        bar_arrive(gid, 32);   // h published

        // ---- latency cover between arrive and wait ----
        {
            float2 o2 = make_float2(hn0, hn1);
            *(float2*)(out + ((size_t)(B0 + cb) * TLEN + t) * 1024
                           + dir * 512 + u0 + cu2 * 2) = o2;
            if (s == TLEN - 1)
                *(float2*)(out + (size_t)BATCH * TLEN * 1024
                               + (size_t)(B0 + cb) * 1024
                               + dir * 512 + u0 + cu2 * 2) = o2;
        }
        if (s + 1 < TLEN) {   // wait for producer, then prefetch xw
            const int tn = dir ? (TLEN - 2 - s) : (s + 1);
            while (*(volatile unsigned int*)&g_done[tn] < (unsigned)TILES_PER_T) { }
            const float* xp = g_xw + ((size_t)tn * NC + dir * 1536 + u0 + cu2 * 2) * BATCH
                              + B0 + cb;
            #pragma unroll
            for (int g = 0; g < 3; g++) {
                xg[g * 2]     = __ldg(xp + (size_t)g * 512 * BATCH);
                xg[g * 2 + 1] = __ldg(xp + ((size_t)g * 512 + 1) * BATCH);
            }
        }
        bar_wait(gid, gen);
        gen++;
    }

    // reset flags for next launch (after ALL 128 blocks finished)
    {
        unsigned int g4 = *(volatile unsigned int*)&g_gen[4].v;
        bar_arrive(4, 128);
        bar_wait(4, g4);
        if (tid < 4) g_done[bid * 4 + tid] = 0u;
    }
}

// ---------------- concurrent-stream setup (pre-main, once) -------------------
static cudaStream_t g_s2 = 0;
static cudaEvent_t  g_evA = 0, g_evB = 0;
static bool         g_forked = false;
struct StreamInit {
    StreamInit() {
        int lo = 0, hi = 0;
        cudaDeviceGetStreamPriorityRange(&lo, &hi);   // lo = LEAST priority
        if (cudaStreamCreateWithPriority(&g_s2, cudaStreamNonBlocking, lo)
                == cudaSuccess &&
            cudaEventCreateWithFlags(&g_evA, cudaEventDisableTiming)
                == cudaSuccess &&
            cudaEventCreateWithFlags(&g_evB, cudaEventDisableTiming)
                == cudaSuccess)
            g_forked = true;
    }
};
static StreamInit g_stream_init;

// ---------------- launch ----------------------------------------------------
extern "C" void kernel_launch(void* const* d_in, const int* in_sizes, int n_in,
                              void* d_out, int out_size)
{
    const int*   tokens = (const int*)  d_in[0];
    const float* emb    = (const float*)d_in[1];
    const float* W_f    = (const float*)d_in[2];
    const float* U_f    = (const float*)d_in[3];
    const float* b_f    = (const float*)d_in[4];
    const float* W_b    = (const float*)d_in[5];
    const float* U_b    = (const float*)d_in[6];
    const float* b_b    = (const float*)d_in[7];
    float* out = (float*)d_out;

    (void)in_sizes; (void)n_in; (void)out_size;

    cudaFuncSetAttribute(embed_gemm, cudaFuncAttributeMaxDynamicSharedMemorySize,
                         EG_SMEM);
    const size_t smem = (512 * 48 + 24 * 576) * sizeof(float); // 153600
    cudaFuncSetAttribute(gru_scan, cudaFuncAttributeMaxDynamicSharedMemorySize,
                         (int)smem);

    dim3 g1(TILES_PER_T, TLEN);

    if (g_forked) {
        // fork: embed on low-priority side stream, scan on main stream
        cudaEventRecord(g_evA, 0);
        cudaStreamWaitEvent(g_s2, g_evA, 0);
        embed_gemm<<<g1, 256, EG_SMEM, g_s2>>>(tokens, emb, W_f, W_b, b_f, b_b);
        cudaEventRecord(g_evB, g_s2);
        gru_scan<<<128, 256, smem>>>(U_f, U_b, b_f, b_b, out);
        cudaStreamWaitEvent(0, g_evB, 0);   // join
    } else {
        // fallback: sequential on one stream (flags trivially satisfied)
        embed_gemm<<<g1, 256, EG_SMEM>>>(tokens, emb, W_f, W_b, b_f, b_b);
        gru_scan<<<128, 256, smem>>>(U_f, U_b, b_f, b_b, out);
    }
}